// round 1
// baseline (speedup 1.0000x reference)
#include <cuda_runtime.h>

// ---------------------------------------------------------------------------
// KAN forward, 2 layers, B=8192, d_in=d_out=1024, spline G=5 order=3 (8 coeff)
// Formulation: per layer, h = Aaug @ Wpack^T where
//   Aaug[b, i*9+0]   = gelu(x[b,i])           (exact erf gelu)
//   Aaug[b, i*9+1+c] = bspline_basis_c(x[b,i])  (Cox-de Boor, 12 knots)
//   Wpack[o, i*9+0]  = base_w[o,i]
//   Wpack[o, i*9+1+c]= spline_w[o,i,c]
// then LayerNorm + PReLU.
// Round 1: fp32 CUDA-core GEMM baseline (correctness + infrastructure).
// ---------------------------------------------------------------------------

#define BATCH 8192
#define DIN   1024
#define DOUT  1024
#define KDIM  (DIN * 9)   // 9216
#define NKNOTS 12

// scratch (device globals: allocation-free rule)
__device__ float g_A[(size_t)BATCH * KDIM];   // 288 MiB augmented activations
__device__ float g_W[(size_t)DOUT * KDIM];    // 36 MiB packed weights
__device__ float g_h[(size_t)BATCH * DOUT];   // pre-LN accumulator
__device__ float g_x[(size_t)BATCH * DOUT];   // layer-1 output

// ---------------------------------------------------------------------------
// Expansion: x -> gelu + 8 B-spline bases, interleaved per input feature.
// ---------------------------------------------------------------------------
__global__ void expand_kernel(const float* __restrict__ xin,
                              const float* __restrict__ grid,
                              int use_internal_x)
{
    int e = blockIdx.x * blockDim.x + threadIdx.x;   // 0 .. BATCH*DIN-1
    int i = e & (DIN - 1);
    float xv = use_internal_x ? g_x[e] : xin[e];

    float gv[NKNOTS];
    const float* g = grid + i * NKNOTS;
#pragma unroll
    for (int j = 0; j < NKNOTS; j++) gv[j] = __ldg(g + j);

    float b[11];
#pragma unroll
    for (int j = 0; j < 11; j++)
        b[j] = (xv >= gv[j] && xv < gv[j + 1]) ? 1.0f : 0.0f;

    // Cox-de Boor, k = 1..3 (mirrors reference exactly; uniform grid so no
    // zero denominators)
#pragma unroll
    for (int j = 0; j < 10; j++)
        b[j] = (xv - gv[j]) / (gv[j + 1] - gv[j]) * b[j]
             + (gv[j + 2] - xv) / (gv[j + 2] - gv[j + 1]) * b[j + 1];
#pragma unroll
    for (int j = 0; j < 9; j++)
        b[j] = (xv - gv[j]) / (gv[j + 2] - gv[j]) * b[j]
             + (gv[j + 3] - xv) / (gv[j + 3] - gv[j + 1]) * b[j + 1];
#pragma unroll
    for (int j = 0; j < 8; j++)
        b[j] = (xv - gv[j]) / (gv[j + 3] - gv[j]) * b[j]
             + (gv[j + 4] - xv) / (gv[j + 4] - gv[j + 1]) * b[j + 1];

    float ge = xv * normcdff(xv);   // exact gelu: x * Phi(x)

    float* outp = g_A + (size_t)(e >> 10) * KDIM + (size_t)i * 9;
    outp[0] = ge;
#pragma unroll
    for (int c = 0; c < 8; c++) outp[1 + c] = b[c];
}

// ---------------------------------------------------------------------------
// Weight packing: interleave base_w + spline_w into [DOUT, KDIM]
// ---------------------------------------------------------------------------
__global__ void pack_w_kernel(const float* __restrict__ bw,
                              const float* __restrict__ sw)
{
    int e = blockIdx.x * blockDim.x + threadIdx.x;   // o*1024 + i
    int i = e & (DIN - 1);
    float* dst = g_W + (size_t)(e >> 10) * KDIM + (size_t)i * 9;
    dst[0] = bw[e];
    const float* s = sw + (size_t)e * 8;
#pragma unroll
    for (int c = 0; c < 8; c++) dst[1 + c] = s[c];
}

// ---------------------------------------------------------------------------
// fp32 GEMM: C[m,n] = sum_k A[m,k] * W[n,k]
// 128x128 CTA tile, BK=8, 8x8 per thread, 256 threads.
// ---------------------------------------------------------------------------
__global__ void __launch_bounds__(256) sgemm_kernel()
{
    __shared__ float As[8][128];
    __shared__ float Bs[8][128];

    const int tid = threadIdx.x;
    const int bm = blockIdx.y * 128;
    const int bn = blockIdx.x * 128;
    const int lrow = tid >> 1;          // 0..127
    const int lcol = (tid & 1) * 4;     // 0 or 4
    const int tx = tid & 15;
    const int ty = tid >> 4;

    const float* Ag = g_A + (size_t)(bm + lrow) * KDIM + lcol;
    const float* Bg = g_W + (size_t)(bn + lrow) * KDIM + lcol;

    float acc[8][8];
#pragma unroll
    for (int r = 0; r < 8; r++)
#pragma unroll
        for (int c = 0; c < 8; c++) acc[r][c] = 0.0f;

    for (int k0 = 0; k0 < KDIM; k0 += 8) {
        float4 av = *(const float4*)(Ag + k0);
        float4 bv = *(const float4*)(Bg + k0);
        As[lcol + 0][lrow] = av.x; As[lcol + 1][lrow] = av.y;
        As[lcol + 2][lrow] = av.z; As[lcol + 3][lrow] = av.w;
        Bs[lcol + 0][lrow] = bv.x; Bs[lcol + 1][lrow] = bv.y;
        Bs[lcol + 2][lrow] = bv.z; Bs[lcol + 3][lrow] = bv.w;
        __syncthreads();

#pragma unroll
        for (int kk = 0; kk < 8; kk++) {
            float ra[8], rb[8];
            *(float4*)&ra[0] = *(const float4*)&As[kk][ty * 8];
            *(float4*)&ra[4] = *(const float4*)&As[kk][ty * 8 + 4];
            *(float4*)&rb[0] = *(const float4*)&Bs[kk][tx * 8];
            *(float4*)&rb[4] = *(const float4*)&Bs[kk][tx * 8 + 4];
#pragma unroll
            for (int r = 0; r < 8; r++)
#pragma unroll
                for (int c = 0; c < 8; c++)
                    acc[r][c] = fmaf(ra[r], rb[c], acc[r][c]);
        }
        __syncthreads();
    }

    float* Cp = g_h + (size_t)(bm + ty * 8) * DOUT + bn + tx * 8;
#pragma unroll
    for (int r = 0; r < 8; r++) {
        *(float4*)(Cp + (size_t)r * DOUT)     = make_float4(acc[r][0], acc[r][1], acc[r][2], acc[r][3]);
        *(float4*)(Cp + (size_t)r * DOUT + 4) = make_float4(acc[r][4], acc[r][5], acc[r][6], acc[r][7]);
    }
}

// ---------------------------------------------------------------------------
// LayerNorm + PReLU. One block per row (1024 cols, 256 threads x float4).
// ---------------------------------------------------------------------------
__global__ void ln_prelu_kernel(const float* __restrict__ gam,
                                const float* __restrict__ bet,
                                const float* __restrict__ pa,
                                float* __restrict__ ext_out,
                                int use_ext_out)
{
    int row = blockIdx.x;
    int tid = threadIdx.x;
    const float4 v = *(const float4*)(g_h + (size_t)row * DOUT + tid * 4);

    float s  = v.x + v.y + v.z + v.w;
    float ss = v.x * v.x + v.y * v.y + v.z * v.z + v.w * v.w;
#pragma unroll
    for (int o = 16; o; o >>= 1) {
        s  += __shfl_down_sync(0xffffffffu, s, o);
        ss += __shfl_down_sync(0xffffffffu, ss, o);
    }
    __shared__ float sm[8], sm2[8];
    if ((tid & 31) == 0) { sm[tid >> 5] = s; sm2[tid >> 5] = ss; }
    __syncthreads();
    float tot = 0.0f, tot2 = 0.0f;
#pragma unroll
    for (int j = 0; j < 8; j++) { tot += sm[j]; tot2 += sm2[j]; }

    const float inv = 1.0f / (float)DOUT;
    float mu   = tot * inv;
    float var  = tot2 * inv - mu * mu;
    float rstd = rsqrtf(var + 1e-5f);
    float a    = __ldg(pa);

    float4 gm = *(const float4*)(gam + tid * 4);
    float4 bt = *(const float4*)(bet + tid * 4);

    float4 o4;
    o4.x = (v.x - mu) * rstd * gm.x + bt.x;
    o4.y = (v.y - mu) * rstd * gm.y + bt.y;
    o4.z = (v.z - mu) * rstd * gm.z + bt.z;
    o4.w = (v.w - mu) * rstd * gm.w + bt.w;
    o4.x = o4.x >= 0.0f ? o4.x : a * o4.x;
    o4.y = o4.y >= 0.0f ? o4.y : a * o4.y;
    o4.z = o4.z >= 0.0f ? o4.z : a * o4.z;
    o4.w = o4.w >= 0.0f ? o4.w : a * o4.w;

    float* dst = use_ext_out ? ext_out : g_x;
    *(float4*)(dst + (size_t)row * DOUT + tid * 4) = o4;
}

// ---------------------------------------------------------------------------
// Launch
// ---------------------------------------------------------------------------
extern "C" void kernel_launch(void* const* d_in, const int* in_sizes, int n_in,
                              void* d_out, int out_size)
{
    const float* x    = (const float*)d_in[0];
    const float* bw   = (const float*)d_in[1];
    const float* sw   = (const float*)d_in[2];
    const float* lng  = (const float*)d_in[3];
    const float* lnb  = (const float*)d_in[4];
    const float* pa   = (const float*)d_in[5];
    const float* grid = (const float*)d_in[6];
    float* out = (float*)d_out;

    const int nexp  = (BATCH * DIN) / 256;   // 32768 blocks
    const int npack = (DOUT * DIN) / 256;    // 4096 blocks
    dim3 ggemm(DOUT / 128, BATCH / 128);     // (8, 64)

    for (int layer = 0; layer < 2; layer++) {
        const size_t wsz = (size_t)DOUT * DIN;
        pack_w_kernel<<<npack, 256>>>(bw + layer * wsz, sw + layer * wsz * 8);
        expand_kernel<<<nexp, 256>>>(x, grid + layer * DIN * NKNOTS, layer);
        sgemm_kernel<<<ggemm, 256>>>();
        ln_prelu_kernel<<<BATCH, 256>>>(lng + layer * DOUT, lnb + layer * DOUT,
                                        pa + layer, out, layer == 1 ? 1 : 0);
    }
}

// round 4
// speedup vs baseline: 2.8803x; 2.8803x over previous
#include <cuda_runtime.h>
#include <cuda_fp16.h>
#include <cstdint>

// ---------------------------------------------------------------------------
// KAN forward, 2 layers, B=8192, d=1024. Fused GEMM:
//   h = Aaug @ Wpack^T, K-layout: [0,1024)=gelu(x_i), [1024,9216)=bases.
// Precision: fp16 hi/lo split, 3-product scheme (hi*hi + hi*lo + lo*hi).
// GEMM: mma.sync.m16n8k16 (HMMA) + cp.async 3-stage pipeline.
// R4 fix: cp.async loader now covers all 8x16B chunks per 128-byte row
// (R3 only wrote half of each row -> uninitialized smem -> NaN).
// ---------------------------------------------------------------------------

#define BATCH 8192
#define DIN   1024
#define DOUT  1024
#define KHALF 9216
#define KSTORE (2*KHALF)     // 18432 (hi | lo)
#define NKNOTS 12

#define TILE_M 128
#define TILE_N 256
#define BK     64
#define KITERS 432           // 3 segments x 144 (27648 / 64)
#define STAGES 3
#define ROWB   144           // 128 data bytes + 16 pad per smem row
#define A_BYTES (TILE_M * ROWB)            // 18432
#define B_BYTES (TILE_N * ROWB)            // 36864
#define STAGE_BYTES (A_BYTES + B_BYTES)    // 55296
#define SMEM_TOTAL (STAGES * STAGE_BYTES)  // 165888

__device__ __align__(128) __half g_A[(size_t)BATCH * KSTORE]; // 302 MiB
__device__ __align__(128) __half g_W[(size_t)DOUT * KSTORE];  // 37.7 MiB
__device__ float g_h[(size_t)BATCH * DOUT];
__device__ float g_x[(size_t)BATCH * DOUT];

// ------------------------------- helpers -----------------------------------
__device__ __forceinline__ uint32_t smem_u32(const void* p) {
    uint32_t a;
    asm("{ .reg .u64 t; cvta.to.shared.u64 t, %1; cvt.u32.u64 %0, t; }" : "=r"(a) : "l"(p));
    return a;
}
__device__ __forceinline__ void cp_async16(uint32_t s, const void* g) {
    asm volatile("cp.async.cg.shared.global [%0], [%1], 16;" :: "r"(s), "l"(g));
}
#define CP_COMMIT() asm volatile("cp.async.commit_group;" ::: "memory")
#define CP_WAIT1()  asm volatile("cp.async.wait_group 1;" ::: "memory")

__device__ __forceinline__ void ldsm_x4(uint32_t& r0, uint32_t& r1, uint32_t& r2,
                                        uint32_t& r3, uint32_t addr) {
    asm volatile("ldmatrix.sync.aligned.m8n8.x4.shared.b16 {%0,%1,%2,%3}, [%4];"
                 : "=r"(r0), "=r"(r1), "=r"(r2), "=r"(r3) : "r"(addr));
}
__device__ __forceinline__ void mma16816(float* d, const uint32_t* a,
                                         uint32_t b0, uint32_t b1) {
    asm volatile("mma.sync.aligned.m16n8k16.row.col.f32.f16.f16.f32 "
                 "{%0,%1,%2,%3}, {%4,%5,%6,%7}, {%8,%9}, {%0,%1,%2,%3};"
                 : "+f"(d[0]), "+f"(d[1]), "+f"(d[2]), "+f"(d[3])
                 : "r"(a[0]), "r"(a[1]), "r"(a[2]), "r"(a[3]), "r"(b0), "r"(b1));
}

// ---------------------------------------------------------------------------
// Expansion: x -> gelu + 8 B-spline bases, fp16 hi/lo split.
// ---------------------------------------------------------------------------
__global__ void expand_kernel(const float* __restrict__ xin,
                              const float* __restrict__ grid,
                              int use_internal_x)
{
    int e = blockIdx.x * blockDim.x + threadIdx.x;
    int i = e & (DIN - 1);
    float xv = use_internal_x ? g_x[e] : xin[e];

    float gv[NKNOTS];
    const float* g = grid + i * NKNOTS;
#pragma unroll
    for (int j = 0; j < NKNOTS; j++) gv[j] = __ldg(g + j);

    float b[11];
#pragma unroll
    for (int j = 0; j < 11; j++)
        b[j] = (xv >= gv[j] && xv < gv[j + 1]) ? 1.0f : 0.0f;
#pragma unroll
    for (int j = 0; j < 10; j++)
        b[j] = (xv - gv[j]) / (gv[j + 1] - gv[j]) * b[j]
             + (gv[j + 2] - xv) / (gv[j + 2] - gv[j + 1]) * b[j + 1];
#pragma unroll
    for (int j = 0; j < 9; j++)
        b[j] = (xv - gv[j]) / (gv[j + 2] - gv[j]) * b[j]
             + (gv[j + 3] - xv) / (gv[j + 3] - gv[j + 1]) * b[j + 1];
#pragma unroll
    for (int j = 0; j < 8; j++)
        b[j] = (xv - gv[j]) / (gv[j + 3] - gv[j]) * b[j]
             + (gv[j + 4] - xv) / (gv[j + 4] - gv[j + 1]) * b[j + 1];

    float ge = xv * normcdff(xv);

    __half* A = g_A + (size_t)(e >> 10) * KSTORE;
    __half gh = __float2half_rn(ge);
    A[i]         = gh;
    A[KHALF + i] = __float2half_rn(ge - __half2float(gh));

    __half hi[8], lo[8];
#pragma unroll
    for (int c = 0; c < 8; c++) {
        hi[c] = __float2half_rn(b[c]);
        lo[c] = __float2half_rn(b[c] - __half2float(hi[c]));
    }
    *(uint4*)(A + DIN + 8 * i)         = *(uint4*)hi;
    *(uint4*)(A + KHALF + DIN + 8 * i) = *(uint4*)lo;
}

// ---------------------------------------------------------------------------
// Weight packing (fp16 hi/lo split, same K layout).
// ---------------------------------------------------------------------------
__global__ void pack_w_kernel(const float* __restrict__ bw,
                              const float* __restrict__ sw)
{
    int e = blockIdx.x * blockDim.x + threadIdx.x;  // o*1024 + i
    int i = e & (DIN - 1);
    __half* W = g_W + (size_t)(e >> 10) * KSTORE;

    float v = bw[e];
    __half h = __float2half_rn(v);
    W[i]         = h;
    W[KHALF + i] = __float2half_rn(v - __half2float(h));

    const float* s = sw + (size_t)e * 8;
    __half hi[8], lo[8];
#pragma unroll
    for (int c = 0; c < 8; c++) {
        float sv = s[c];
        hi[c] = __float2half_rn(sv);
        lo[c] = __float2half_rn(sv - __half2float(hi[c]));
    }
    *(uint4*)(W + DIN + 8 * i)         = *(uint4*)hi;
    *(uint4*)(W + KHALF + DIN + 8 * i) = *(uint4*)lo;
}

// ---------------------------------------------------------------------------
// HMMA GEMM: h[m,n] = sum over 3 segments of A-seg x W-seg.
// CTA 128x256, BK=64, 3-stage cp.async, 8 warps (2x4), warp tile 64x64.
// ---------------------------------------------------------------------------
__global__ void __launch_bounds__(256, 1) gemm_kernel()
{
    extern __shared__ __align__(128) char smem[];
    const uint32_t sb = smem_u32(smem);

    const int tid = threadIdx.x;
    const int wid = tid >> 5;
    const int l   = tid & 31;
    const int wm  = wid >> 2;        // 0..1
    const int wn  = wid & 3;         // 0..3
    const int bm  = blockIdx.y * TILE_M;
    const int bn  = blockIdx.x * TILE_N;

    // cp.async: thread owns row (tid>>3) in each 32-row set, chunk (tid&7).
    // A: 4 sets of 32 rows (128), B: 8 sets of 32 rows (256); 8 chunks/row.
    const int ld_row = tid >> 3;     // 0..31
    const int ld_kc  = tid & 7;      // 0..7
    const __half* gA = g_A + (size_t)(bm + ld_row) * KSTORE + ld_kc * 8;
    const __half* gB = g_W + (size_t)(bn + ld_row) * KSTORE + ld_kc * 8;
    const uint32_t sA = sb + ld_row * ROWB + ld_kc * 16;
    const uint32_t sBs = sb + A_BYTES + ld_row * ROWB + ld_kc * 16;

    // ldmatrix per-thread source offsets
    const uint32_t a_lrow = (uint32_t)(l & 15);
    const uint32_t a_lkb  = (uint32_t)((l >> 4) * 16);        // bytes
    const uint32_t b_lrow = (uint32_t)((l & 7) + ((l & 16) >> 1));
    const uint32_t b_lkb  = (uint32_t)((l & 8) * 2);          // bytes

    float acc[4][8][4];
#pragma unroll
    for (int i = 0; i < 4; i++)
#pragma unroll
        for (int j = 0; j < 8; j++)
#pragma unroll
            for (int r = 0; r < 4; r++) acc[i][j][r] = 0.0f;

    // ---- stage loader: 12 cp.async x 16B per thread = full 48KB stage ----
    auto issue = [&](int it, int stage) {
        int seg = it / 144;
        int w   = it - seg * 144;
        size_t ka = (size_t)((seg == 2 ? KHALF : 0) + w * BK);
        size_t kb = (size_t)((seg == 1 ? KHALF : 0) + w * BK);
        uint32_t so = (uint32_t)(stage * STAGE_BYTES);
        const __half* ga = gA + ka;
        const __half* gb = gB + kb;
#pragma unroll
        for (int q = 0; q < 4; q++)
            cp_async16(sA + so + q * 32 * ROWB, ga + (size_t)q * 32 * KSTORE);
#pragma unroll
        for (int q = 0; q < 8; q++)
            cp_async16(sBs + so + q * 32 * ROWB, gb + (size_t)q * 32 * KSTORE);
    };

    issue(0, 0); CP_COMMIT();
    issue(1, 1); CP_COMMIT();

    for (int it = 0; it < KITERS; it++) {
        int cur = it % STAGES;
        CP_WAIT1();
        __syncthreads();
        if (it + 2 < KITERS) issue(it + 2, (it + 2) % STAGES);
        CP_COMMIT();

        const uint32_t As = sb + cur * STAGE_BYTES;
        const uint32_t Bs = As + A_BYTES;

#pragma unroll
        for (int kk = 0; kk < 4; kk++) {
            uint32_t a[4][4], b[4][4];
#pragma unroll
            for (int i = 0; i < 4; i++)
                ldsm_x4(a[i][0], a[i][1], a[i][2], a[i][3],
                        As + (wm * 64 + i * 16 + a_lrow) * ROWB + kk * 32 + a_lkb);
#pragma unroll
            for (int j2 = 0; j2 < 4; j2++)
                ldsm_x4(b[j2][0], b[j2][1], b[j2][2], b[j2][3],
                        Bs + (wn * 64 + j2 * 16 + b_lrow) * ROWB + kk * 32 + b_lkb);
#pragma unroll
            for (int i = 0; i < 4; i++)
#pragma unroll
                for (int j = 0; j < 8; j++)
                    mma16816(acc[i][j], a[i], b[j >> 1][(j & 1) * 2],
                             b[j >> 1][(j & 1) * 2 + 1]);
        }
    }

    // ---- epilogue: regs -> g_h ----
    const int g = l >> 2;
    const int t = l & 3;
    const int row0 = bm + wm * 64 + g;
    const int col0 = bn + wn * 64 + t * 2;
#pragma unroll
    for (int i = 0; i < 4; i++) {
#pragma unroll
        for (int j = 0; j < 8; j++) {
            float* p0 = g_h + (size_t)(row0 + i * 16) * DOUT + col0 + j * 8;
            float* p1 = p0 + 8 * DOUT;
            *(float2*)p0 = make_float2(acc[i][j][0], acc[i][j][1]);
            *(float2*)p1 = make_float2(acc[i][j][2], acc[i][j][3]);
        }
    }
}

// ---------------------------------------------------------------------------
// LayerNorm + PReLU
// ---------------------------------------------------------------------------
__global__ void ln_prelu_kernel(const float* __restrict__ gam,
                                const float* __restrict__ bet,
                                const float* __restrict__ pa,
                                float* __restrict__ ext_out,
                                int use_ext_out)
{
    int row = blockIdx.x;
    int tid = threadIdx.x;
    const float4 v = *(const float4*)(g_h + (size_t)row * DOUT + tid * 4);

    float s  = v.x + v.y + v.z + v.w;
    float ss = v.x * v.x + v.y * v.y + v.z * v.z + v.w * v.w;
#pragma unroll
    for (int o = 16; o; o >>= 1) {
        s  += __shfl_down_sync(0xffffffffu, s, o);
        ss += __shfl_down_sync(0xffffffffu, ss, o);
    }
    __shared__ float sm[8], sm2[8];
    if ((tid & 31) == 0) { sm[tid >> 5] = s; sm2[tid >> 5] = ss; }
    __syncthreads();
    float tot = 0.0f, tot2 = 0.0f;
#pragma unroll
    for (int j = 0; j < 8; j++) { tot += sm[j]; tot2 += sm2[j]; }

    const float inv = 1.0f / (float)DOUT;
    float mu   = tot * inv;
    float var  = tot2 * inv - mu * mu;
    float rstd = rsqrtf(var + 1e-5f);
    float a    = __ldg(pa);

    float4 gm = *(const float4*)(gam + tid * 4);
    float4 bt = *(const float4*)(bet + tid * 4);

    float4 o4;
    o4.x = (v.x - mu) * rstd * gm.x + bt.x;
    o4.y = (v.y - mu) * rstd * gm.y + bt.y;
    o4.z = (v.z - mu) * rstd * gm.z + bt.z;
    o4.w = (v.w - mu) * rstd * gm.w + bt.w;
    o4.x = o4.x >= 0.0f ? o4.x : a * o4.x;
    o4.y = o4.y >= 0.0f ? o4.y : a * o4.y;
    o4.z = o4.z >= 0.0f ? o4.z : a * o4.z;
    o4.w = o4.w >= 0.0f ? o4.w : a * o4.w;

    float* dst = use_ext_out ? ext_out : g_x;
    *(float4*)(dst + (size_t)row * DOUT + tid * 4) = o4;
}

// ---------------------------------------------------------------------------
// Launch
// ---------------------------------------------------------------------------
extern "C" void kernel_launch(void* const* d_in, const int* in_sizes, int n_in,
                              void* d_out, int out_size)
{
    const float* x    = (const float*)d_in[0];
    const float* bw   = (const float*)d_in[1];
    const float* sw   = (const float*)d_in[2];
    const float* lng  = (const float*)d_in[3];
    const float* lnb  = (const float*)d_in[4];
    const float* pa   = (const float*)d_in[5];
    const float* grid = (const float*)d_in[6];
    float* out = (float*)d_out;

    cudaFuncSetAttribute(gemm_kernel, cudaFuncAttributeMaxDynamicSharedMemorySize,
                         SMEM_TOTAL);

    const int nexp  = (BATCH * DIN) / 256;
    const int npack = (DOUT * DIN) / 256;
    dim3 ggemm(DOUT / TILE_N, BATCH / TILE_M);   // (4, 64)

    for (int layer = 0; layer < 2; layer++) {
        const size_t wsz = (size_t)DOUT * DIN;
        pack_w_kernel<<<npack, 256>>>(bw + layer * wsz, sw + layer * wsz * 8);
        expand_kernel<<<nexp, 256>>>(x, grid + layer * DIN * NKNOTS, layer);
        gemm_kernel<<<ggemm, 256, SMEM_TOTAL>>>();
        ln_prelu_kernel<<<BATCH, 256>>>(lng + layer * DOUT, lnb + layer * DOUT,
                                        pa + layer, out, layer == 1 ? 1 : 0);
    }
}